// round 8
// baseline (speedup 1.0000x reference)
#include <cuda_runtime.h>
#include <cuda_bf16.h>
#include <cstdint>

#define ROW_LEN 4096
#define THREADS 256
#define V4 4   // 4096 floats / 4 per float4 / 256 threads

__global__ void __launch_bounds__(THREADS, 8)
quant_rowwise_wt(const float* __restrict__ x, float* __restrict__ out)
{
    const size_t base = (size_t)blockIdx.x * ROW_LEN;
    const float4* __restrict__ xr   = reinterpret_cast<const float4*>(x + base);
    float4* __restrict__       outr = reinterpret_cast<float4*>(out + base);

    const int t = threadIdx.x;

    // Front-batched vector loads: 4 independent LDG.128.cs per thread.
    float4 v[V4];
#pragma unroll
    for (int k = 0; k < V4; ++k)
        v[k] = __ldcs(&xr[t + k * THREADS]);

    // Local min/max over 16 values
    float mn = v[0].x, mx = v[0].x;
#pragma unroll
    for (int k = 0; k < V4; ++k) {
        mn = fminf(mn, fminf(fminf(v[k].x, v[k].y), fminf(v[k].z, v[k].w)));
        mx = fmaxf(mx, fmaxf(fmaxf(v[k].x, v[k].y), fmaxf(v[k].z, v[k].w)));
    }

    // Warp reduce
#pragma unroll
    for (int off = 16; off > 0; off >>= 1) {
        mn = fminf(mn, __shfl_xor_sync(0xFFFFFFFFu, mn, off));
        mx = fmaxf(mx, __shfl_xor_sync(0xFFFFFFFFu, mx, off));
    }

    // Block reduce: leaders publish, ONE barrier, every thread folds the
    // 8 partials and computes scale/zp redundantly.
    __shared__ float smn[8], smx[8];
    const int wid = t >> 5;
    const int lid = t & 31;
    if (lid == 0) { smn[wid] = mn; smx[wid] = mx; }
    __syncthreads();

    float bmn = smn[0], bmx = smx[0];
#pragma unroll
    for (int i = 1; i < 8; ++i) {
        bmn = fminf(bmn, smn[i]);
        bmx = fmaxf(bmx, smx[i]);
    }
    float scale = (bmx - bmn) * (1.0f / 255.0f);
    scale = fminf(fmaxf(scale, 1e-5f), 1e4f);
    float zp = -bmn / scale;
    zp = fminf(fmaxf(zp, -1e4f), 1e4f);
    const float inv = 1.0f / scale;

    // Fake quant-dequant; WRITE-THROUGH stores (st.global.wt): no L2
    // dirty-line allocation, no lazy writeback competing with the read stream.
#pragma unroll
    for (int k = 0; k < V4; ++k) {
        float4 r;
        float q;
        q = rintf(v[k].x * inv) + zp; q = fminf(fmaxf(q, 0.0f), 255.0f); r.x = (q - zp) * scale;
        q = rintf(v[k].y * inv) + zp; q = fminf(fmaxf(q, 0.0f), 255.0f); r.y = (q - zp) * scale;
        q = rintf(v[k].z * inv) + zp; q = fminf(fmaxf(q, 0.0f), 255.0f); r.z = (q - zp) * scale;
        q = rintf(v[k].w * inv) + zp; q = fminf(fmaxf(q, 0.0f), 255.0f); r.w = (q - zp) * scale;
        __stwt(&outr[t + k * THREADS], r);
    }
}

extern "C" void kernel_launch(void* const* d_in, const int* in_sizes, int n_in,
                              void* d_out, int out_size)
{
    const float* x = (const float*)d_in[0];
    float* out = (float*)d_out;
    const int n_rows = in_sizes[0] / ROW_LEN;   // 16384
    quant_rowwise_wt<<<n_rows, THREADS>>>(x, out);
}

// round 9
// speedup vs baseline: 1.0051x; 1.0051x over previous
#include <cuda_runtime.h>
#include <cuda_bf16.h>
#include <cstdint>

#define ROW_LEN 4096
#define THREADS 128
#define V4 8   // 4096 floats / 4 per float4 / 128 threads

__global__ void __launch_bounds__(THREADS, 8)
quant_rowwise_128(const float* __restrict__ x, float* __restrict__ out)
{
    const size_t base = (size_t)blockIdx.x * ROW_LEN;
    const float4* __restrict__ xr   = reinterpret_cast<const float4*>(x + base);
    float4* __restrict__       outr = reinterpret_cast<float4*>(out + base);

    const int t = threadIdx.x;

    // Front-batched vector loads: 8 consecutive independent LDG.128.cs per
    // thread (MLP_p1 = 8) — deepest load queue at issue time.
    float4 v[V4];
#pragma unroll
    for (int k = 0; k < V4; ++k)
        v[k] = __ldcs(&xr[t + k * THREADS]);

    // Local min/max over 32 values, 2 independent chains for ILP
    float mn0 = v[0].x, mx0 = v[0].x;
    float mn1 = v[1].x, mx1 = v[1].x;
#pragma unroll
    for (int k = 0; k < V4; k += 2) {
        mn0 = fminf(mn0, fminf(fminf(v[k+0].x, v[k+0].y), fminf(v[k+0].z, v[k+0].w)));
        mx0 = fmaxf(mx0, fmaxf(fmaxf(v[k+0].x, v[k+0].y), fmaxf(v[k+0].z, v[k+0].w)));
        mn1 = fminf(mn1, fminf(fminf(v[k+1].x, v[k+1].y), fminf(v[k+1].z, v[k+1].w)));
        mx1 = fmaxf(mx1, fmaxf(fmaxf(v[k+1].x, v[k+1].y), fmaxf(v[k+1].z, v[k+1].w)));
    }
    float mn = fminf(mn0, mn1);
    float mx = fmaxf(mx0, mx1);

    // Warp reduce
#pragma unroll
    for (int off = 16; off > 0; off >>= 1) {
        mn = fminf(mn, __shfl_xor_sync(0xFFFFFFFFu, mn, off));
        mx = fmaxf(mx, __shfl_xor_sync(0xFFFFFFFFu, mx, off));
    }

    // Block reduce across only 4 warps: leaders publish, ONE barrier,
    // every thread folds the 4 partials redundantly.
    __shared__ float smn[4], smx[4];
    const int wid = t >> 5;
    const int lid = t & 31;
    if (lid == 0) { smn[wid] = mn; smx[wid] = mx; }
    __syncthreads();

    float bmn = fminf(fminf(smn[0], smn[1]), fminf(smn[2], smn[3]));
    float bmx = fmaxf(fmaxf(smx[0], smx[1]), fmaxf(smx[2], smx[3]));

    float scale = (bmx - bmn) * (1.0f / 255.0f);
    scale = fminf(fmaxf(scale, 1e-5f), 1e4f);
    float zp = -bmn / scale;
    zp = fminf(fmaxf(zp, -1e4f), 1e4f);
    const float inv = 1.0f / scale;

    // Fake quant-dequant, streaming vector stores
#pragma unroll
    for (int k = 0; k < V4; ++k) {
        float4 r;
        float q;
        q = rintf(v[k].x * inv) + zp; q = fminf(fmaxf(q, 0.0f), 255.0f); r.x = (q - zp) * scale;
        q = rintf(v[k].y * inv) + zp; q = fminf(fmaxf(q, 0.0f), 255.0f); r.y = (q - zp) * scale;
        q = rintf(v[k].z * inv) + zp; q = fminf(fmaxf(q, 0.0f), 255.0f); r.z = (q - zp) * scale;
        q = rintf(v[k].w * inv) + zp; q = fminf(fmaxf(q, 0.0f), 255.0f); r.w = (q - zp) * scale;
        __stcs(&outr[t + k * THREADS], r);
    }
}

extern "C" void kernel_launch(void* const* d_in, const int* in_sizes, int n_in,
                              void* d_out, int out_size)
{
    const float* x = (const float*)d_in[0];
    float* out = (float*)d_out;
    const int n_rows = in_sizes[0] / ROW_LEN;   // 16384
    quant_rowwise_128<<<n_rows, THREADS>>>(x, out);
}